// round 8
// baseline (speedup 1.0000x reference)
#include <cuda_runtime.h>

// ---------------------------------------------------------------------------
// B=8192 rows, R=2, K0=3072; tree 3072 ->(f=3) 1024 ->(f=2)... -> 1
// k1: grid (32 rowblocks, 16 spans, 2 r). Block = 256 rows x 192 leaves x 1 r.
//     R-split halves register/live state -> no spills at 4 blocks/SM.
//     Synapse + levels 0..5 (scalar carry chain) -> K=32 scratch [r][node][row].
// k2: 512 blocks x 128 thr; thread=(row16, r, quarter) folds levels 6..8,
//     16 threads/block fold 9..10 + root combine.
// ---------------------------------------------------------------------------

#define NROWS   8192
#define SPAN    192
#define XSTRIDE 28

__device__ float g_n32[2 * 32 * NROWS];   // [r][node][row]

struct K1Params {
    const float *x, *ap1, *ap2, *am1, *am2, *g0;
    const float *w0, *b0, *w1, *b1, *w2, *b2, *w3, *b3, *w4, *b4, *w5, *b5;
};
struct K2Params {
    const float *w6, *b6, *w7, *b7, *w8, *b8, *w9, *b9, *w10, *b10;
    const float *root_w, *root_b;
    float* out;
};

__device__ __forceinline__ float ex2f(float x) {
    float y; asm("ex2.approx.ftz.f32 %0, %1;" : "=f"(y) : "f"(x)); return y;
}
__device__ __forceinline__ float rcpf(float x) {
    float y; asm("rcp.approx.ftz.f32 %0, %1;" : "=f"(y) : "f"(x)); return y;
}
__device__ __forceinline__ float leaky(float y) {
    return fmaxf(y, 0.01f * y);
}

__global__ void __launch_bounds__(256, 4) k1_lower(K1Params P)
{
    __shared__ __align__(16) float s_x[256 * XSTRIDE];   // 16B-aligned: float4 access
    __shared__ float4 s_p4[SPAN];             // a1*L2E, a2*L2E, m1*L2E, m2*L2E
    __shared__ float2 s_gw[SPAN];             // g0*5, w0
    __shared__ float  s_b0[64], s_w1[64], s_b1[32], s_w2[32], s_b2[16],
                      s_w3[16], s_b3[8], s_w4[8], s_b4[4], s_w5[4], s_b5[2];

    const int tid  = threadIdx.x;
    const int r0   = blockIdx.x * 256;
    const int span = blockIdx.y;
    const int rr   = blockIdx.z;              // repeat index (0/1)
    const int k0   = span * SPAN;
    const int row  = r0 + tid;
    const float L2E = 1.4426950408889634f;

    // ---- stage + prescale synapse params for this r (coalesced) ----
    if (tid < SPAN) {
        int idx = rr * 3072 + k0 + tid;
        s_p4[tid] = make_float4(P.ap1[idx] * L2E, P.ap2[idx] * L2E,
                                P.am1[idx] * L2E, P.am2[idx] * L2E);
        s_gw[tid] = make_float2(P.g0[idx] * 5.0f, P.w0[idx]);
    }
    // ---- stage level params (this r only) ----
    if (tid < 64)       {                 s_b0[tid]   = P.b0[rr*1024 + span*64 + tid]; }
    else if (tid < 128) { int u=tid-64;   s_w1[u]     = P.w1[rr*1024 + span*64 + u]; }
    else if (tid < 160) { int u=tid-128;  s_b1[u]     = P.b1[rr*512  + span*32 + u]; }
    else if (tid < 192) { int u=tid-160;  s_w2[u]     = P.w2[rr*512  + span*32 + u]; }
    else if (tid < 208) { int u=tid-192;  s_b2[u]     = P.b2[rr*256  + span*16 + u]; }
    else if (tid < 224) { int u=tid-208;  s_w3[u]     = P.w3[rr*256  + span*16 + u]; }
    else if (tid < 232) { int u=tid-224;  s_b3[u]     = P.b3[rr*128  + span*8  + u]; }
    else if (tid < 240) { int u=tid-232;  s_w4[u]     = P.w4[rr*128  + span*8  + u]; }
    else if (tid < 244) { int u=tid-240;  s_b4[u]     = P.b4[rr*64   + span*4  + u]; }
    else if (tid < 248) { int u=tid-244;  s_w5[u]     = P.w5[rr*64   + span*4  + u]; }
    else if (tid < 250) { int u=tid-248;  s_b5[u]     = P.b5[rr*32   + span*2  + u]; }

    const float* xbase = P.x + (size_t)r0 * 3072 + k0;
    float c3, c4, c5;

#pragma unroll
    for (int c = 0; c < 8; ++c) {              // 8 chunks of 24 leaves
        __syncthreads();
        // cooperative coalesced x load: 256 rows x 24 floats
#pragma unroll
        for (int it = 0; it < 6; ++it) {
            int i  = it * 256 + tid;
            int rw = i / 6, cc = i - rw * 6;
            float4 v = *(const float4*)(xbase + (size_t)rw * 3072 + c * 24 + cc * 4);
            *(float4*)&s_x[rw * XSTRIDE + cc * 4] = v;
        }
        __syncthreads();

#pragma unroll
        for (int nc = 0; nc < 2; ++nc) {
            const int g = c * 2 + nc;          // group 0..15 (compile-time)

            float xs[12];
#pragma unroll
            for (int q = 0; q < 3; ++q) {
                float4 v = *(const float4*)&s_x[tid * XSTRIDE + nc * 12 + q * 4];
                xs[q*4+0]=v.x; xs[q*4+1]=v.y; xs[q*4+2]=v.z; xs[q*4+3]=v.w;
            }

            float n1[4];
#pragma unroll
            for (int i2 = 0; i2 < 4; ++i2) {
                float acc = s_b0[g * 4 + i2];
#pragma unroll
                for (int t = 0; t < 3; ++t) {
                    const int leaf = g * 12 + 3 * i2 + t;
                    float4 p  = s_p4[leaf];
                    float2 gw = s_gw[leaf];
                    float xv  = xs[3 * i2 + t];
                    float gp  = ex2f(fmaf(p.x, xv, p.y));
                    float gm  = ex2f(fmaf(p.z, xv, p.w));
                    float den = fmaf(0.2f, gw.x, gp + gm);
                    float num = fmaf(gp, 120.f, gw.x);
                    acc = fmaf(fmaf(num, rcpf(den), -70.f), gw.y, acc);
                }
                n1[i2] = leaky(acc);
            }
            float n2a = leaky(fmaf(n1[1], s_w1[4*g+1], fmaf(n1[0], s_w1[4*g+0], s_b1[2*g+0])));
            float n2b = leaky(fmaf(n1[3], s_w1[4*g+3], fmaf(n1[2], s_w1[4*g+2], s_b1[2*g+1])));
            float v   = leaky(fmaf(n2b,  s_w2[2*g+1], fmaf(n2a,  s_w2[2*g+0], s_b2[g])));

            // carry-chain merge, levels 3..5 (g compile-time)
            if ((g & 1) == 0) { c3 = v; }
            else {
                const int p3 = g >> 1;
                v = leaky(fmaf(v, s_w3[2*p3+1], fmaf(c3, s_w3[2*p3], s_b3[p3])));
                if ((g & 3) == 1) { c4 = v; }
                else {
                    const int p4i = g >> 2;
                    v = leaky(fmaf(v, s_w4[2*p4i+1], fmaf(c4, s_w4[2*p4i], s_b4[p4i])));
                    if ((g & 7) == 3) { c5 = v; }
                    else {
                        const int p5 = g >> 3;
                        v = leaky(fmaf(v, s_w5[2*p5+1], fmaf(c5, s_w5[2*p5], s_b5[p5])));
                        g_n32[((size_t)(rr * 32 + span * 2 + p5) << 13) + row] = v;
                    }
                }
            }
        }
    }
}

// ---- k2: K=32 -> 1, thread = (row16, r, quarter); 512 blocks x 128 --------
__global__ void __launch_bounds__(128) k2_upper(K2Params P)
{
    __shared__ float s_part[8 * 16];          // [plane][row16]

    const int tid   = threadIdx.x;
    const int row16 = tid & 15;
    const int plane = tid >> 4;               // 0..7
    const int r     = plane >> 2;
    const int q     = plane & 3;              // quarter: nodes 8q..8q+7
    const int row   = blockIdx.x * 16 + row16;

    const float* src = g_n32 + ((size_t)r << 18) + ((size_t)(q * 8) << 13) + row;
    float v[8];
#pragma unroll
    for (int i = 0; i < 8; ++i) v[i] = src[(size_t)i << 13];

    float u[4];
#pragma unroll
    for (int j = 0; j < 4; ++j) {
        int n = 4 * q + j;
        u[j] = leaky(fmaf(v[2*j+1], __ldg(P.w6 + r*32 + 2*n + 1),
                     fmaf(v[2*j],   __ldg(P.w6 + r*32 + 2*n),
                          __ldg(P.b6 + r*16 + n))));
    }
    float t[2];
#pragma unroll
    for (int j = 0; j < 2; ++j) {
        int n = 2 * q + j;
        t[j] = leaky(fmaf(u[2*j+1], __ldg(P.w7 + r*16 + 2*n + 1),
                     fmaf(u[2*j],   __ldg(P.w7 + r*16 + 2*n),
                          __ldg(P.b7 + r*8 + n))));
    }
    float p8 = leaky(fmaf(t[1], __ldg(P.w8 + r*8 + 2*q + 1),
                     fmaf(t[0], __ldg(P.w8 + r*8 + 2*q),
                          __ldg(P.b8 + r*4 + q))));
    s_part[plane * 16 + row16] = p8;
    __syncthreads();

    if (tid < 16) {
        float y[2];
#pragma unroll
        for (int r2 = 0; r2 < 2; ++r2) {
            float a0 = s_part[(r2*4+0)*16 + tid];
            float a1 = s_part[(r2*4+1)*16 + tid];
            float a2 = s_part[(r2*4+2)*16 + tid];
            float a3 = s_part[(r2*4+3)*16 + tid];
            float z0 = leaky(fmaf(a1, __ldg(P.w9 + r2*4 + 1),
                             fmaf(a0, __ldg(P.w9 + r2*4),     __ldg(P.b9 + r2*2))));
            float z1 = leaky(fmaf(a3, __ldg(P.w9 + r2*4 + 3),
                             fmaf(a2, __ldg(P.w9 + r2*4 + 2), __ldg(P.b9 + r2*2 + 1))));
            y[r2] = leaky(fmaf(z1, __ldg(P.w10 + r2*2 + 1),
                          fmaf(z0, __ldg(P.w10 + r2*2),       __ldg(P.b10 + r2))));
        }
        P.out[blockIdx.x * 16 + tid] =
            fmaf(y[1], __ldg(P.root_w + 1),
            fmaf(y[0], __ldg(P.root_w), __ldg(P.root_b)));
    }
}

extern "C" void kernel_launch(void* const* d_in, const int* in_sizes, int n_in,
                              void* d_out, int out_size)
{
    const float* w[11];
    const float* b[11];
    bool interleaved = (in_sizes[8] == 2048);
    for (int i = 0; i < 11; ++i) {
        if (interleaved) {
            w[i] = (const float*)d_in[6 + 2 * i];
            b[i] = (const float*)d_in[7 + 2 * i];
        } else {
            w[i] = (const float*)d_in[6 + i];
            b[i] = (const float*)d_in[17 + i];
        }
    }

    K1Params P1;
    P1.x   = (const float*)d_in[0];
    P1.ap1 = (const float*)d_in[1];
    P1.ap2 = (const float*)d_in[2];
    P1.am1 = (const float*)d_in[3];
    P1.am2 = (const float*)d_in[4];
    P1.g0  = (const float*)d_in[5];
    P1.w0 = w[0]; P1.b0 = b[0];
    P1.w1 = w[1]; P1.b1 = b[1];
    P1.w2 = w[2]; P1.b2 = b[2];
    P1.w3 = w[3]; P1.b3 = b[3];
    P1.w4 = w[4]; P1.b4 = b[4];
    P1.w5 = w[5]; P1.b5 = b[5];
    k1_lower<<<dim3(32, 16, 2), 256>>>(P1);

    K2Params P2;
    P2.w6 = w[6];  P2.b6 = b[6];
    P2.w7 = w[7];  P2.b7 = b[7];
    P2.w8 = w[8];  P2.b8 = b[8];
    P2.w9 = w[9];  P2.b9 = b[9];
    P2.w10 = w[10]; P2.b10 = b[10];
    P2.root_w = (const float*)d_in[28];
    P2.root_b = (const float*)d_in[29];
    P2.out    = (float*)d_out;
    k2_upper<<<512, 128>>>(P2);
}

// round 9
// speedup vs baseline: 1.3669x; 1.3669x over previous
#include <cuda_runtime.h>

// ---------------------------------------------------------------------------
// B=8192 rows, R=2, K0=3072; tree 3072 ->(f=3) 1024 ->(f=2)... -> 1
// k1: R4 structure: block = 256 rows x 192-leaf span, combined r loop,
//     chunk=24 staging, launch_bounds(256,4). xs reloaded from smem inside
//     the r loop to cut live registers below the 64-reg cap (no spills).
//     Synapse + levels 0..5 -> K=32 scratch [r][node][row] (2MB).
// k2: 512 blocks x 128 thr; thread=(row16, r, quarter) folds levels 6..8,
//     16 threads/block fold 9..10 + root combine.
// ---------------------------------------------------------------------------

#define NROWS   8192
#define SPAN    192
#define XSTRIDE 28

__device__ float g_n32[2 * 32 * NROWS];   // [r][node][row]

struct K1Params {
    const float *x, *ap1, *ap2, *am1, *am2, *g0;
    const float *w0, *b0, *w1, *b1, *w2, *b2, *w3, *b3, *w4, *b4, *w5, *b5;
};
struct K2Params {
    const float *w6, *b6, *w7, *b7, *w8, *b8, *w9, *b9, *w10, *b10;
    const float *root_w, *root_b;
    float* out;
};

__device__ __forceinline__ float ex2f(float x) {
    float y; asm("ex2.approx.ftz.f32 %0, %1;" : "=f"(y) : "f"(x)); return y;
}
__device__ __forceinline__ float rcpf(float x) {
    float y; asm("rcp.approx.ftz.f32 %0, %1;" : "=f"(y) : "f"(x)); return y;
}
__device__ __forceinline__ float leaky(float y) {
    return fmaxf(y, 0.01f * y);
}

__global__ void __launch_bounds__(256, 4) k1_lower(K1Params P)
{
    __shared__ __align__(16) float s_x[256 * XSTRIDE];
    __shared__ float4 s_p4[2][SPAN];          // a1*L2E, a2*L2E, m1*L2E, m2*L2E
    __shared__ float2 s_gw[2][SPAN];          // g0*5, w0
    __shared__ float  s_b0[2][64], s_w1[2][64], s_b1[2][32], s_w2[2][32],
                      s_b2[2][16], s_w3[2][16], s_b3[2][8],  s_w4[2][8],
                      s_b4[2][4],  s_w5[2][4],  s_b5[2][2];

    const int tid  = threadIdx.x;
    const int r0   = blockIdx.x * 256;
    const int span = blockIdx.y;
    const int k0   = span * SPAN;
    const int row  = r0 + tid;
    const float L2E = 1.4426950408889634f;

    // ---- stage + prescale synapse params (coalesced per array) ----
    for (int i = tid; i < 2 * SPAN; i += 256) {
        int r = i / SPAN, j = i - r * SPAN;
        int idx = r * 3072 + k0 + j;
        s_p4[r][j] = make_float4(P.ap1[idx] * L2E, P.ap2[idx] * L2E,
                                 P.am1[idx] * L2E, P.am2[idx] * L2E);
        s_gw[r][j] = make_float2(P.g0[idx] * 5.0f, P.w0[idx]);
    }
    if (tid < 128)      { int r=tid>>6, j=tid&63;            s_b0[r][j] = P.b0[r*1024 + span*64 + j]; }
    else                { int u=tid-128, r=u>>6, j=u&63;     s_w1[r][j] = P.w1[r*1024 + span*64 + j]; }
    if (tid < 64)       { int r=tid>>5, j=tid&31;            s_b1[r][j] = P.b1[r*512 + span*32 + j]; }
    else if (tid < 128) { int u=tid-64,  r=u>>5, j=u&31;     s_w2[r][j] = P.w2[r*512 + span*32 + j]; }
    else if (tid < 160) { int u=tid-128, r=u>>4, j=u&15;     s_b2[r][j] = P.b2[r*256 + span*16 + j]; }
    else if (tid < 192) { int u=tid-160, r=u>>4, j=u&15;     s_w3[r][j] = P.w3[r*256 + span*16 + j]; }
    else if (tid < 208) { int u=tid-192, r=u>>3, j=u&7;      s_b3[r][j] = P.b3[r*128 + span*8 + j]; }
    else if (tid < 224) { int u=tid-208, r=u>>3, j=u&7;      s_w4[r][j] = P.w4[r*128 + span*8 + j]; }
    else if (tid < 232) { int u=tid-224, r=u>>2, j=u&3;      s_b4[r][j] = P.b4[r*64 + span*4 + j]; }
    else if (tid < 240) { int u=tid-232, r=u>>2, j=u&3;      s_w5[r][j] = P.w5[r*64 + span*4 + j]; }
    else if (tid < 244) { int u=tid-240, r=u>>1, j=u&1;      s_b5[r][j] = P.b5[r*32 + span*2 + j]; }

    const float* xbase = P.x + (size_t)r0 * 3072 + k0;
    float c3[2], c4[2], c5[2];

#pragma unroll
    for (int c = 0; c < 8; ++c) {              // 8 chunks of 24 leaves
        __syncthreads();
        // cooperative coalesced x load: 256 rows x 24 floats
#pragma unroll
        for (int it = 0; it < 6; ++it) {
            int i  = it * 256 + tid;
            int rw = i / 6, cc = i - rw * 6;
            float4 v = __ldcs((const float4*)(xbase + (size_t)rw * 3072 + c * 24 + cc * 4));
            *(float4*)&s_x[rw * XSTRIDE + cc * 4] = v;
        }
        __syncthreads();

#pragma unroll
        for (int nc = 0; nc < 2; ++nc) {
            const int g = c * 2 + nc;          // group 0..15 (compile-time)

#pragma unroll
            for (int r = 0; r < 2; ++r) {
                // reload this half-chunk's 12 leaves per r: keeps the live
                // range inside the r iteration (register pressure < 64)
                float xs[12];
#pragma unroll
                for (int q = 0; q < 3; ++q) {
                    float4 v = *(const float4*)&s_x[tid * XSTRIDE + nc * 12 + q * 4];
                    xs[q*4+0]=v.x; xs[q*4+1]=v.y; xs[q*4+2]=v.z; xs[q*4+3]=v.w;
                }

                float n1[4];
#pragma unroll
                for (int i2 = 0; i2 < 4; ++i2) {
                    float acc = s_b0[r][g * 4 + i2];
#pragma unroll
                    for (int t = 0; t < 3; ++t) {
                        const int leaf = g * 12 + 3 * i2 + t;
                        float4 p  = s_p4[r][leaf];
                        float2 gw = s_gw[r][leaf];
                        float xv  = xs[3 * i2 + t];
                        float gp  = ex2f(fmaf(p.x, xv, p.y));
                        float gm  = ex2f(fmaf(p.z, xv, p.w));
                        float den = fmaf(0.2f, gw.x, gp + gm);
                        float num = fmaf(gp, 120.f, gw.x);
                        acc = fmaf(fmaf(num, rcpf(den), -70.f), gw.y, acc);
                    }
                    n1[i2] = leaky(acc);
                }
                float n2a = leaky(fmaf(n1[1], s_w1[r][4*g+1], fmaf(n1[0], s_w1[r][4*g+0], s_b1[r][2*g+0])));
                float n2b = leaky(fmaf(n1[3], s_w1[r][4*g+3], fmaf(n1[2], s_w1[r][4*g+2], s_b1[r][2*g+1])));
                float v   = leaky(fmaf(n2b,  s_w2[r][2*g+1], fmaf(n2a,  s_w2[r][2*g+0], s_b2[r][g])));

                // carry-chain merge, levels 3..5 (g compile-time)
                if ((g & 1) == 0) { c3[r] = v; }
                else {
                    const int p3 = g >> 1;
                    v = leaky(fmaf(v, s_w3[r][2*p3+1], fmaf(c3[r], s_w3[r][2*p3], s_b3[r][p3])));
                    if ((g & 3) == 1) { c4[r] = v; }
                    else {
                        const int p4i = g >> 2;
                        v = leaky(fmaf(v, s_w4[r][2*p4i+1], fmaf(c4[r], s_w4[r][2*p4i], s_b4[r][p4i])));
                        if ((g & 7) == 3) { c5[r] = v; }
                        else {
                            const int p5 = g >> 3;
                            v = leaky(fmaf(v, s_w5[r][2*p5+1], fmaf(c5[r], s_w5[r][2*p5], s_b5[r][p5])));
                            g_n32[((size_t)(r * 32 + span * 2 + p5) << 13) + row] = v;
                        }
                    }
                }
            }
        }
    }
}

// ---- k2: K=32 -> 1, thread = (row16, r, quarter); 512 blocks x 128 --------
__global__ void __launch_bounds__(128) k2_upper(K2Params P)
{
    __shared__ float s_part[8 * 16];          // [plane][row16]

    const int tid   = threadIdx.x;
    const int row16 = tid & 15;
    const int plane = tid >> 4;               // 0..7
    const int r     = plane >> 2;
    const int q     = plane & 3;              // quarter: nodes 8q..8q+7
    const int row   = blockIdx.x * 16 + row16;

    const float* src = g_n32 + ((size_t)r << 18) + ((size_t)(q * 8) << 13) + row;
    float v[8];
#pragma unroll
    for (int i = 0; i < 8; ++i) v[i] = src[(size_t)i << 13];

    float u[4];
#pragma unroll
    for (int j = 0; j < 4; ++j) {
        int n = 4 * q + j;
        u[j] = leaky(fmaf(v[2*j+1], __ldg(P.w6 + r*32 + 2*n + 1),
                     fmaf(v[2*j],   __ldg(P.w6 + r*32 + 2*n),
                          __ldg(P.b6 + r*16 + n))));
    }
    float t[2];
#pragma unroll
    for (int j = 0; j < 2; ++j) {
        int n = 2 * q + j;
        t[j] = leaky(fmaf(u[2*j+1], __ldg(P.w7 + r*16 + 2*n + 1),
                     fmaf(u[2*j],   __ldg(P.w7 + r*16 + 2*n),
                          __ldg(P.b7 + r*8 + n))));
    }
    float p8 = leaky(fmaf(t[1], __ldg(P.w8 + r*8 + 2*q + 1),
                     fmaf(t[0], __ldg(P.w8 + r*8 + 2*q),
                          __ldg(P.b8 + r*4 + q))));
    s_part[plane * 16 + row16] = p8;
    __syncthreads();

    if (tid < 16) {
        float y[2];
#pragma unroll
        for (int r2 = 0; r2 < 2; ++r2) {
            float a0 = s_part[(r2*4+0)*16 + tid];
            float a1 = s_part[(r2*4+1)*16 + tid];
            float a2 = s_part[(r2*4+2)*16 + tid];
            float a3 = s_part[(r2*4+3)*16 + tid];
            float z0 = leaky(fmaf(a1, __ldg(P.w9 + r2*4 + 1),
                             fmaf(a0, __ldg(P.w9 + r2*4),     __ldg(P.b9 + r2*2))));
            float z1 = leaky(fmaf(a3, __ldg(P.w9 + r2*4 + 3),
                             fmaf(a2, __ldg(P.w9 + r2*4 + 2), __ldg(P.b9 + r2*2 + 1))));
            y[r2] = leaky(fmaf(z1, __ldg(P.w10 + r2*2 + 1),
                          fmaf(z0, __ldg(P.w10 + r2*2),       __ldg(P.b10 + r2))));
        }
        P.out[blockIdx.x * 16 + tid] =
            fmaf(y[1], __ldg(P.root_w + 1),
            fmaf(y[0], __ldg(P.root_w), __ldg(P.root_b)));
    }
}

extern "C" void kernel_launch(void* const* d_in, const int* in_sizes, int n_in,
                              void* d_out, int out_size)
{
    const float* w[11];
    const float* b[11];
    bool interleaved = (in_sizes[8] == 2048);
    for (int i = 0; i < 11; ++i) {
        if (interleaved) {
            w[i] = (const float*)d_in[6 + 2 * i];
            b[i] = (const float*)d_in[7 + 2 * i];
        } else {
            w[i] = (const float*)d_in[6 + i];
            b[i] = (const float*)d_in[17 + i];
        }
    }

    K1Params P1;
    P1.x   = (const float*)d_in[0];
    P1.ap1 = (const float*)d_in[1];
    P1.ap2 = (const float*)d_in[2];
    P1.am1 = (const float*)d_in[3];
    P1.am2 = (const float*)d_in[4];
    P1.g0  = (const float*)d_in[5];
    P1.w0 = w[0]; P1.b0 = b[0];
    P1.w1 = w[1]; P1.b1 = b[1];
    P1.w2 = w[2]; P1.b2 = b[2];
    P1.w3 = w[3]; P1.b3 = b[3];
    P1.w4 = w[4]; P1.b4 = b[4];
    P1.w5 = w[5]; P1.b5 = b[5];
    k1_lower<<<dim3(32, 16), 256>>>(P1);

    K2Params P2;
    P2.w6 = w[6];  P2.b6 = b[6];
    P2.w7 = w[7];  P2.b7 = b[7];
    P2.w8 = w[8];  P2.b8 = b[8];
    P2.w9 = w[9];  P2.b9 = b[9];
    P2.w10 = w[10]; P2.b10 = b[10];
    P2.root_w = (const float*)d_in[28];
    P2.root_b = (const float*)d_in[29];
    P2.out    = (float*)d_out;
    k2_upper<<<512, 128>>>(P2);
}